// round 13
// baseline (speedup 1.0000x reference)
#include <cuda_runtime.h>
#include <cuda_bf16.h>
#include <math.h>
#include <stdint.h>

#define BB   8
#define CC   128
#define NN   4096
#define NLAB 16
// slots: 0,1 = own-row sums (wn=0/1); 2 + (d-1) = combined col sums, d=1..16
#define NSLOT 18
#define NCTA  (BB * 32)

// ---------------------------------------------------------------------------
// Device scratch (no allocations allowed)
// ---------------------------------------------------------------------------
__device__ __nv_bfloat16 g_vt[BB * NN * CC];     // normalized (x sqrt(log2e)) [b][n][c]
__device__ unsigned char g_lab8[BB * NN];
__device__ int           g_cnt[BB * NLAB];
__device__ float2        g_stage[BB * 32 * NSLOT * 128];  // (pos, tot) partials
__device__ float         g_part[BB * 32];
__device__ unsigned int  g_sync0, g_sync1, g_ctr;   // zero-init; reset at kernel end

// ---------------------------------------------------------------------------
// smem layout. Tile rows padded to 272B (conflict-free LDSM).
// Phase 0 aliases: ts[128][129] floats over A/B0 region; rinv/ssp in SM_CS.
// Phase 2 aliases: sp2/st2/red in SM_CS region.
// ---------------------------------------------------------------------------
#define ROWB   272
#define TILEB  (128 * ROWB)          // 34816
#define SM_A   0
#define SM_B0  TILEB
#define SM_B1  (2 * TILEB)
#define SM_LAB (3 * TILEB)           // 4096 B labels
#define SM_CS  (SM_LAB + 4096)       // 4096 B: scol / rinv+ssp / sp2+st2+red
#define SMEM_DYN (SM_CS + 4096)      // 112640 B -> 2 CTAs/SM guaranteed

// ---------------------------------------------------------------------------
// PTX helpers (plain sm_80+ features)
// ---------------------------------------------------------------------------
__device__ __forceinline__ uint32_t s2u(const void* p) {
    return (uint32_t)__cvta_generic_to_shared(p);
}
__device__ __forceinline__ void cp16(uint32_t dst, const void* src) {
    asm volatile("cp.async.cg.shared.global [%0], [%1], 16;" :: "r"(dst), "l"(src) : "memory");
}
__device__ __forceinline__ void cp_commit() { asm volatile("cp.async.commit_group;" ::: "memory"); }
__device__ __forceinline__ void cp_wait0()  { asm volatile("cp.async.wait_group 0;" ::: "memory"); }

__device__ __forceinline__ void ldsm4(uint32_t* r, uint32_t addr) {
    asm volatile("ldmatrix.sync.aligned.m8n8.x4.shared.b16 {%0,%1,%2,%3}, [%4];"
                 : "=r"(r[0]), "=r"(r[1]), "=r"(r[2]), "=r"(r[3]) : "r"(addr));
}
__device__ __forceinline__ void mma16816(float* c, const uint32_t* a,
                                         uint32_t b0, uint32_t b1) {
    asm volatile(
        "mma.sync.aligned.m16n8k16.row.col.f32.bf16.bf16.f32 "
        "{%0,%1,%2,%3}, {%4,%5,%6,%7}, {%8,%9}, {%0,%1,%2,%3};"
        : "+f"(c[0]), "+f"(c[1]), "+f"(c[2]), "+f"(c[3])
        : "r"(a[0]), "r"(a[1]), "r"(a[2]), "r"(a[3]), "r"(b0), "r"(b1));
}
__device__ __forceinline__ float ex2(float x) {
    float y; asm("ex2.approx.f32 %0, %1;" : "=f"(y) : "f"(x)); return y;
}

// Grid-wide barrier: safe because all NCTA blocks are co-resident (occ 2,
// 256 <= 148*2). threadfenceReduction pattern: per-thread fence, one arrival.
__device__ __forceinline__ void grid_sync(unsigned int* ctr) {
    __threadfence();
    __syncthreads();
    if (threadIdx.x == 0) {
        atomicAdd(ctr, 1u);
        while (atomicAdd(ctr, 0u) < (unsigned)NCTA) __nanosleep(64);
    }
    __syncthreads();
    __threadfence();
}

// ---------------------------------------------------------------------------
// One 128x128 tile, full 32x64 warp strip. MMA + exp + row sums (regs) +
// col sums -> scol (smem).
// ---------------------------------------------------------------------------
template <bool DIAG>
__device__ __forceinline__ void do_tile(
    uint32_t aB, uint32_t bB, int i0, int j0,
    int wm, int wn, int lane,
    const int rl[2][2], const unsigned char* __restrict__ lab8s,
    float pos[2][2], float tot[2][2], float* __restrict__ scol)
{
    const int lrow = lane & 15;
    const int lkof = (lane >> 4) << 3;

    float acc[2][8][4];
#pragma unroll
    for (int mt = 0; mt < 2; mt++)
#pragma unroll
        for (int nt = 0; nt < 8; nt++)
#pragma unroll
            for (int r = 0; r < 4; r++) acc[mt][nt][r] = 0.f;

#pragma unroll
    for (int ks = 0; ks < 8; ks++) {
        const int k0 = ks * 16;
        uint32_t a[2][4], bq[4][4];
#pragma unroll
        for (int mt = 0; mt < 2; mt++) {
            int row = wm * 32 + mt * 16 + lrow;
            ldsm4(a[mt], aB + row * ROWB + (k0 + lkof) * 2);
        }
#pragma unroll
        for (int q = 0; q < 4; q++) {
            int row = wn * 64 + q * 16 + lrow;
            ldsm4(bq[q], bB + row * ROWB + (k0 + lkof) * 2);
        }
#pragma unroll
        for (int mt = 0; mt < 2; mt++)
#pragma unroll
            for (int q = 0; q < 4; q++) {
                mma16816(acc[mt][2 * q],     a[mt], bq[q][0], bq[q][2]);
                mma16816(acc[mt][2 * q + 1], a[mt], bq[q][1], bq[q][3]);
            }
    }

#pragma unroll
    for (int g = 0; g < 2; g++) {
        int cl0[4], cl1[4];
#pragma unroll
        for (int n4 = 0; n4 < 4; n4++) {
            int jj = j0 + wn * 64 + (g * 4 + n4) * 8 + (lane & 3) * 2;
            cl0[n4] = (int)lab8s[jj];
            cl1[n4] = (int)lab8s[jj + 1];
        }

        float cpos[4][2], ctot[4][2];
        if (!DIAG) {
#pragma unroll
            for (int n4 = 0; n4 < 4; n4++) {
                cpos[n4][0] = cpos[n4][1] = 0.f;
                ctot[n4][0] = ctot[n4][1] = 0.f;
            }
        }

#pragma unroll
        for (int mt = 0; mt < 2; mt++)
#pragma unroll
            for (int u = 0; u < 2; u++) {
                const int rlab = rl[mt][u];
                float tsum = 0.f, psum = 0.f;
#pragma unroll
                for (int n4 = 0; n4 < 4; n4++) {
                    const int nt = g * 4 + n4;
                    float e0 = ex2(acc[mt][nt][2 * u]);
                    float e1 = ex2(acc[mt][nt][2 * u + 1]);
                    if (DIAG) {
                        const int gi = i0 + wm * 32 + mt * 16 + (lane >> 2) + u * 8;
                        const int gj = j0 + wn * 64 + nt * 8 + (lane & 3) * 2;
                        if (gi == gj)     e0 = 0.f;
                        if (gi == gj + 1) e1 = 0.f;
                    }
                    const bool m0 = (cl0[n4] == rlab);
                    const bool m1 = (cl1[n4] == rlab);
                    tsum += e0 + e1;
                    if (m0) psum += e0;
                    if (m1) psum += e1;
                    if (!DIAG) {
                        ctot[n4][0] += e0;
                        ctot[n4][1] += e1;
                        if (m0) cpos[n4][0] += e0;
                        if (m1) cpos[n4][1] += e1;
                    }
                }
                tot[mt][u] += tsum;
                pos[mt][u] += psum;
            }

        if (!DIAG) {
#pragma unroll
            for (int n4 = 0; n4 < 4; n4++)
#pragma unroll
                for (int e = 0; e < 2; e++) {
                    float cp = cpos[n4][e], ct = ctot[n4][e];
                    cp += __shfl_xor_sync(0xFFFFFFFF, cp, 4);
                    cp += __shfl_xor_sync(0xFFFFFFFF, cp, 8);
                    cp += __shfl_xor_sync(0xFFFFFFFF, cp, 16);
                    ct += __shfl_xor_sync(0xFFFFFFFF, ct, 4);
                    ct += __shfl_xor_sync(0xFFFFFFFF, ct, 8);
                    ct += __shfl_xor_sync(0xFFFFFFFF, ct, 16);
                    if (lane < 4) {
                        int col = wn * 64 + (g * 4 + n4) * 8 + lane * 2 + e;
                        scol[(wm * 128 + col) * 2 + 0] = cp;
                        scol[(wm * 128 + col) * 2 + 1] = ct;
                    }
                }
        }
    }
}

// ---------------------------------------------------------------------------
// The fused kernel: norm -> gridsync -> gram -> gridsync -> combine+loss
// ---------------------------------------------------------------------------
__global__ __launch_bounds__(256, 2) void k_all(
    const float* __restrict__ f, const int* __restrict__ labels,
    float* __restrict__ out)
{
    extern __shared__ char sm[];
    __shared__ int hist[NLAB];
    __shared__ int s_last;
    const uint32_t sb = s2u(sm);

    const int b    = blockIdx.y;
    const int it   = blockIdx.x;
    const int i0   = it * 128;
    const int tid  = threadIdx.x;
    const int wid  = tid >> 5;
    const int lane = tid & 31;
    const int wm   = wid & 3;
    const int wn   = wid >> 2;
    const int npair = (it < 16) ? 17 : 16;
    const int blk  = b * 32 + it;

    // ===================== Phase 0: normalize + transpose =====================
    {
        float* ts   = (float*)sm;                       // [128][129]
        float* ssp  = (float*)(sm + SM_CS);             // 256 partials
        float* rinv = (float*)(sm + SM_CS + 1024);      // 128

        if (it == 0) {
            if (tid < NLAB) hist[tid] = 0;
            __syncthreads();
            for (int n = tid; n < NN; n += 256) {
                int l = labels[b * NN + n];
                g_lab8[b * NN + n] = (unsigned char)l;
                atomicAdd(&hist[l], 1);
            }
            __syncthreads();
            if (tid < NLAB) g_cnt[b * NLAB + tid] = hist[tid];
        }

        const float* fb = f + (size_t)b * CC * NN;
#pragma unroll 4
        for (int t = 0; t < 64; t++) {
            int idx = tid + t * 256;
            int k = idx >> 7, n = idx & 127;
            ts[n * 129 + k] = fb[(size_t)k * NN + i0 + n];
        }
        __syncthreads();
        {
            int n = tid & 127, kh = (tid >> 7) * 64;
            float ss = 0.f;
#pragma unroll 8
            for (int k = 0; k < 64; k++) {
                float x = ts[n * 129 + kh + k];
                ss = fmaf(x, x, ss);
            }
            ssp[tid] = ss;
        }
        __syncthreads();
        if (tid < 128)
            rinv[tid] = 1.2011224087864498f
                      / fmaxf(sqrtf(ssp[tid] + ssp[tid + 128]), 1e-12f);
        __syncthreads();
        __nv_bfloat162* o2 = (__nv_bfloat162*)g_vt;
#pragma unroll 4
        for (int t = 0; t < 32; t++) {
            int idx = tid + t * 256;
            int n = idx >> 6, c2 = idx & 63;
            float r = rinv[n];
            float v0 = ts[n * 129 + 2 * c2] * r;
            float v1 = ts[n * 129 + 2 * c2 + 1] * r;
            o2[((size_t)b * NN + i0 + n) * 64 + c2] = __floats2bfloat162_rn(v0, v1);
        }
    }
    grid_sync(&g_sync0);

    // ===================== Phase 1: symmetric HMMA gram =====================
    {
        unsigned char* lab8s = (unsigned char*)(sm + SM_LAB);
        float* scol = (float*)(sm + SM_CS);
        const __nv_bfloat16* vt = g_vt + (size_t)b * NN * CC;

#pragma unroll
        for (int t = 0; t < 8; t++) {
            int idx = tid + t * 256;
            int row = idx >> 4, c16 = idx & 15;
            cp16(sb + SM_A + row * ROWB + c16 * 16,
                 vt + (size_t)(i0 + row) * CC + c16 * 8);
            cp16(sb + SM_B0 + row * ROWB + c16 * 16,
                 vt + (size_t)(i0 + row) * CC + c16 * 8);
        }
        cp16(sb + SM_LAB + tid * 16, g_lab8 + (size_t)b * NN + tid * 16);
        cp_commit();
        cp_wait0();
        __syncthreads();

        int rl[2][2];
#pragma unroll
        for (int mt = 0; mt < 2; mt++)
#pragma unroll
            for (int u = 0; u < 2; u++)
                rl[mt][u] = (int)lab8s[i0 + wm * 32 + mt * 16 + (lane >> 2) + u * 8];

        float pos[2][2] = {{0.f, 0.f}, {0.f, 0.f}};
        float tot[2][2] = {{0.f, 0.f}, {0.f, 0.f}};

        for (int d = 0; d < npair; d++) {
            const int jt  = (it + d) & 31;
            const int cur = d & 1;
            if (d + 1 < npair) {
                const int j0n = ((it + d + 1) & 31) * 128;
                uint32_t bdst = sb + (cur ? SM_B0 : SM_B1);
#pragma unroll
                for (int t = 0; t < 8; t++) {
                    int idx = tid + t * 256;
                    int row = idx >> 4, c16 = idx & 15;
                    cp16(bdst + row * ROWB + c16 * 16,
                         vt + (size_t)(j0n + row) * CC + c16 * 8);
                }
                cp_commit();
            }

            const uint32_t aB = sb + SM_A;
            const uint32_t bB = sb + (cur ? SM_B1 : SM_B0);
            const int j0 = jt * 128;

            if (d == 0)
                do_tile<true>(aB, bB, i0, j0, wm, wn, lane, rl, lab8s, pos, tot, scol);
            else
                do_tile<false>(aB, bB, i0, j0, wm, wn, lane, rl, lab8s, pos, tot, scol);

            __syncthreads();
            if (d > 0 && tid < 128) {
                float p = scol[(0 * 128 + tid) * 2]     + scol[(1 * 128 + tid) * 2]
                        + scol[(2 * 128 + tid) * 2]     + scol[(3 * 128 + tid) * 2];
                float t = scol[(0 * 128 + tid) * 2 + 1] + scol[(1 * 128 + tid) * 2 + 1]
                        + scol[(2 * 128 + tid) * 2 + 1] + scol[(3 * 128 + tid) * 2 + 1];
                g_stage[((size_t)(b * 32 + jt) * NSLOT + 2 + (d - 1)) * 128 + tid]
                    = make_float2(p, t);
            }
            cp_wait0();
            __syncthreads();
        }

        // own-row sums -> slots 0 (wn=0) and 1 (wn=1)
#pragma unroll
        for (int mt = 0; mt < 2; mt++)
#pragma unroll
            for (int u = 0; u < 2; u++) {
                float p = pos[mt][u], t = tot[mt][u];
                p += __shfl_xor_sync(0xFFFFFFFF, p, 1);
                p += __shfl_xor_sync(0xFFFFFFFF, p, 2);
                t += __shfl_xor_sync(0xFFFFFFFF, t, 1);
                t += __shfl_xor_sync(0xFFFFFFFF, t, 2);
                if ((lane & 3) == 0) {
                    int row = wm * 32 + mt * 16 + (lane >> 2) + u * 8;
                    g_stage[((size_t)blk * NSLOT + wn) * 128 + row]
                        = make_float2(p, t);
                }
            }
    }
    grid_sync(&g_sync1);

    // ===================== Phase 2: combine + loss =====================
    {
        unsigned char* lab8s = (unsigned char*)(sm + SM_LAB);  // still valid
        float* sp2 = (float*)(sm + SM_CS);             // [2][128]
        float* st2 = (float*)(sm + SM_CS + 1024);      // [2][128]
        float* red = (float*)(sm + SM_CS + 2048);      // [256]

        const float2* stg = g_stage + (size_t)blk * NSLOT * 128;
        const int r = tid & 127;
        const int q = tid >> 7;                        // stripe 0/1

        float p = 0.f, tt = 0.f;
        {   // own-row slot q
            float2 v = stg[q * 128 + r];
            p += v.x; tt += v.y;
        }
#pragma unroll
        for (int s = 2 + q; s < NSLOT; s += 2) {
            if (s == 17 && it < 16) break;             // d=16 only if it >= 16
            float2 v = stg[s * 128 + r];
            p += v.x; tt += v.y;
        }
        sp2[q * 128 + r] = p;
        st2[q * 128 + r] = tt;
        __syncthreads();

        if (tid < 128) {
            float pp = sp2[tid] + sp2[128 + tid];
            float tq = st2[tid] + st2[128 + tid];
            int l = (int)lab8s[i0 + tid];
            int cnt = g_cnt[b * NLAB + l];
            float pm = pp / (float)cnt;
            float nm = (tq - pp) / (float)(NN - cnt);
            red[tid] = __logf((pm + nm) / pm);
        } else {
            red[tid] = 0.f;
        }
        __syncthreads();
        if (tid < 64) red[tid] += red[tid + 64];
        __syncthreads();
        if (tid < 32) {
            float v = red[tid] + red[tid + 32];
#pragma unroll
            for (int o = 16; o > 0; o >>= 1) v += __shfl_xor_sync(0xFFFFFFFF, v, o);
            if (tid == 0) {
                g_part[blk] = v;
                __threadfence();
                s_last = (atomicAdd(&g_ctr, 1u) == (unsigned)(NCTA - 1));
            }
        }
        __syncthreads();
        if (s_last) {
            __threadfence();
            red[tid] = g_part[tid];
            __syncthreads();
            if (tid < 128) red[tid] += red[tid + 128];
            __syncthreads();
            if (tid < 64) red[tid] += red[tid + 64];
            __syncthreads();
            if (tid < 32) {
                float v = red[tid] + red[tid + 32];
#pragma unroll
                for (int o = 16; o > 0; o >>= 1) v += __shfl_xor_sync(0xFFFFFFFF, v, o);
                if (tid == 0) {
                    out[0] = v / (float)(BB * NN);
                    // safe reset: all CTAs have passed both spins and g_ctr
                    g_sync0 = 0u; g_sync1 = 0u; g_ctr = 0u;
                    __threadfence();
                }
            }
        }
    }
}

// ---------------------------------------------------------------------------
extern "C" void kernel_launch(void* const* d_in, const int* in_sizes, int n_in,
                              void* d_out, int out_size) {
    const float* f   = (const float*)d_in[0];
    const int*   lab = (const int*)d_in[1];
    float*       out = (float*)d_out;

    cudaFuncSetAttribute(k_all, cudaFuncAttributeMaxDynamicSharedMemorySize,
                         SMEM_DYN);

    k_all<<<dim3(32, BB), 256, SMEM_DYN>>>(f, lab, out);
}

// round 14
// speedup vs baseline: 1.0365x; 1.0365x over previous
#include <cuda_runtime.h>
#include <cuda_bf16.h>
#include <math.h>
#include <stdint.h>

#define BB   8
#define CC   128
#define NN   4096
#define NLAB 16
// slots: 0,1 = own-row sums (wn=0/1); 2 + (d-1) = combined col sums, d=1..16
#define NSLOT 18

// ---------------------------------------------------------------------------
// Device scratch (no allocations allowed)
// ---------------------------------------------------------------------------
__device__ __nv_bfloat16 g_vt[BB * NN * CC];     // normalized (x sqrt(log2e)) [b][n][c]
__device__ unsigned char g_lab8[BB * NN];
__device__ int           g_cnt[BB * NLAB];
__device__ float2        g_stage[BB * 32 * NSLOT * 128];  // (pos, tot) partials
__device__ float         g_part[BB * 32];
__device__ unsigned int  g_ctr;

// ---------------------------------------------------------------------------
// smem layout for k_gram. Tile rows padded to 272B (conflict-free LDSM).
// ---------------------------------------------------------------------------
#define ROWB   272
#define TILEB  (128 * ROWB)          // 34816
#define SM_A   0
#define SM_B0  TILEB
#define SM_B1  (2 * TILEB)
#define SM_LAB (3 * TILEB)           // 4096 B labels
#define SM_CS  (SM_LAB + 4096)       // 4096 B col partials [4 wm][128 col][2]
#define SMEM_DYN (SM_CS + 4096)      // 112640 B -> 2 CTAs/SM

// k_norm smem: ts[128*129] + ssp[512] + srinv[128] floats
#define NORM_SMEM ((128 * 129 + 512 + 128) * 4)

// ---------------------------------------------------------------------------
// PTX helpers (plain sm_80+ features)
// ---------------------------------------------------------------------------
__device__ __forceinline__ uint32_t s2u(const void* p) {
    return (uint32_t)__cvta_generic_to_shared(p);
}
__device__ __forceinline__ void cp16(uint32_t dst, const void* src) {
    asm volatile("cp.async.cg.shared.global [%0], [%1], 16;" :: "r"(dst), "l"(src) : "memory");
}
__device__ __forceinline__ void cp_commit() { asm volatile("cp.async.commit_group;" ::: "memory"); }
__device__ __forceinline__ void cp_wait0()  { asm volatile("cp.async.wait_group 0;" ::: "memory"); }

__device__ __forceinline__ void ldsm4(uint32_t* r, uint32_t addr) {
    asm volatile("ldmatrix.sync.aligned.m8n8.x4.shared.b16 {%0,%1,%2,%3}, [%4];"
                 : "=r"(r[0]), "=r"(r[1]), "=r"(r[2]), "=r"(r[3]) : "r"(addr));
}
__device__ __forceinline__ void mma16816(float* c, const uint32_t* a,
                                         uint32_t b0, uint32_t b1) {
    asm volatile(
        "mma.sync.aligned.m16n8k16.row.col.f32.bf16.bf16.f32 "
        "{%0,%1,%2,%3}, {%4,%5,%6,%7}, {%8,%9}, {%0,%1,%2,%3};"
        : "+f"(c[0]), "+f"(c[1]), "+f"(c[2]), "+f"(c[3])
        : "r"(a[0]), "r"(a[1]), "r"(a[2]), "r"(a[3]), "r"(b0), "r"(b1));
}
__device__ __forceinline__ float ex2(float x) {
    float y; asm("ex2.approx.f32 %0, %1;" : "=f"(y) : "f"(x)); return y;
}

// ---------------------------------------------------------------------------
// Kernel A: labels -> uint8 copy + per-cloud histogram (+ counter reset)
// ---------------------------------------------------------------------------
__global__ void k_labels(const int* __restrict__ labels) {
    __shared__ int hist[NLAB];
    int b = blockIdx.x;
    if (b == 0 && threadIdx.x == 0) g_ctr = 0;
    if (threadIdx.x < NLAB) hist[threadIdx.x] = 0;
    __syncthreads();
    for (int n = threadIdx.x; n < NN; n += blockDim.x) {
        int l = labels[b * NN + n];
        g_lab8[b * NN + n] = (unsigned char)l;
        atomicAdd(&hist[l], 1);
    }
    __syncthreads();
    if (threadIdx.x < NLAB) g_cnt[b * NLAB + threadIdx.x] = hist[threadIdx.x];
}

// ---------------------------------------------------------------------------
// Kernel B: normalize (x sqrt(log2e)) + transpose + bf16: g_vt[b][n][c]
// 512 threads. Load phase: 8 fully-unrolled LDG.128 per thread (MLP 8).
// Norm: 4 threads per column, smem combine.
// ---------------------------------------------------------------------------
__global__ __launch_bounds__(512) void k_norm(const float* __restrict__ f) {
    extern __shared__ float ts[];               // [128][129]
    float* ssp   = ts + 128 * 129;              // [512] quarter sums
    float* srinv = ssp + 512;                   // [128]
    const int b = blockIdx.y, n0 = blockIdx.x * 128;
    const int tid = threadIdx.x;

    // ---- load + transpose: 4096 float4, 8 per thread, full MLP ----
    const float4* f4 = (const float4*)(f + (size_t)b * CC * NN);
    const int n0q = n0 >> 2;
    float4 v[8];
#pragma unroll
    for (int t = 0; t < 8; t++) {
        int idx = tid + t * 512;                // float4 index
        int k = idx >> 5, n4 = idx & 31;        // 32 float4 per 128-wide row
        v[t] = f4[(size_t)k * (NN / 4) + n0q + n4];
    }
#pragma unroll
    for (int t = 0; t < 8; t++) {
        int idx = tid + t * 512;
        int k = idx >> 5, n4 = (idx & 31) << 2;
        ts[(n4 + 0) * 129 + k] = v[t].x;
        ts[(n4 + 1) * 129 + k] = v[t].y;
        ts[(n4 + 2) * 129 + k] = v[t].z;
        ts[(n4 + 3) * 129 + k] = v[t].w;
    }
    __syncthreads();

    // ---- column norms: 4 threads per column (32 k each) ----
    {
        const int n = tid & 127, q = tid >> 7;
        float ss = 0.f;
#pragma unroll 8
        for (int k = 0; k < 32; k++) {
            float x = ts[n * 129 + q * 32 + k];
            ss = fmaf(x, x, ss);
        }
        ssp[tid] = ss;
    }
    __syncthreads();
    if (tid < 128) {
        float s = ssp[tid] + ssp[tid + 128] + ssp[tid + 256] + ssp[tid + 384];
        srinv[tid] = 1.2011224087864498f / fmaxf(sqrtf(s), 1e-12f);
    }
    __syncthreads();

    // ---- scale + bf16 convert + write [n][c] ----
    __nv_bfloat162* o2 = (__nv_bfloat162*)g_vt;
#pragma unroll
    for (int t = 0; t < 16; t++) {
        int idx = tid + t * 512;
        int n = idx >> 6, c2 = idx & 63;
        float r = srinv[n];
        float v0 = ts[n * 129 + 2 * c2] * r;
        float v1 = ts[n * 129 + 2 * c2 + 1] * r;
        o2[((size_t)b * NN + n0 + n) * 64 + c2] = __floats2bfloat162_rn(v0, v1);
    }
}

// ---------------------------------------------------------------------------
// One 128x128 tile, full 32x64 warp strip (A-fragments reused across cols).
// MMA + exp + row sums (registers) + col sums -> scol (smem).
// ---------------------------------------------------------------------------
template <bool DIAG>
__device__ __forceinline__ void do_tile(
    uint32_t aB, uint32_t bB, int i0, int j0,
    int wm, int wn, int lane,
    const int rl[2][2], const unsigned char* __restrict__ lab8s,
    float pos[2][2], float tot[2][2], float* __restrict__ scol)
{
    const int lrow = lane & 15;
    const int lkof = (lane >> 4) << 3;

    float acc[2][8][4];
#pragma unroll
    for (int mt = 0; mt < 2; mt++)
#pragma unroll
        for (int nt = 0; nt < 8; nt++)
#pragma unroll
            for (int r = 0; r < 4; r++) acc[mt][nt][r] = 0.f;

#pragma unroll
    for (int ks = 0; ks < 8; ks++) {
        const int k0 = ks * 16;
        uint32_t a[2][4], bq[4][4];
#pragma unroll
        for (int mt = 0; mt < 2; mt++) {
            int row = wm * 32 + mt * 16 + lrow;
            ldsm4(a[mt], aB + row * ROWB + (k0 + lkof) * 2);
        }
#pragma unroll
        for (int q = 0; q < 4; q++) {
            int row = wn * 64 + q * 16 + lrow;
            ldsm4(bq[q], bB + row * ROWB + (k0 + lkof) * 2);
        }
#pragma unroll
        for (int mt = 0; mt < 2; mt++)
#pragma unroll
            for (int q = 0; q < 4; q++) {
                mma16816(acc[mt][2 * q],     a[mt], bq[q][0], bq[q][2]);
                mma16816(acc[mt][2 * q + 1], a[mt], bq[q][1], bq[q][3]);
            }
    }

    // epilogue in two 4-nt groups (caps live col-partial registers)
#pragma unroll
    for (int g = 0; g < 2; g++) {
        int cl0[4], cl1[4];
#pragma unroll
        for (int n4 = 0; n4 < 4; n4++) {
            int jj = j0 + wn * 64 + (g * 4 + n4) * 8 + (lane & 3) * 2;
            cl0[n4] = (int)lab8s[jj];
            cl1[n4] = (int)lab8s[jj + 1];
        }

        float cpos[4][2], ctot[4][2];
        if (!DIAG) {
#pragma unroll
            for (int n4 = 0; n4 < 4; n4++) {
                cpos[n4][0] = cpos[n4][1] = 0.f;
                ctot[n4][0] = ctot[n4][1] = 0.f;
            }
        }

#pragma unroll
        for (int mt = 0; mt < 2; mt++)
#pragma unroll
            for (int u = 0; u < 2; u++) {
                const int rlab = rl[mt][u];
                float tsum = 0.f, psum = 0.f;
#pragma unroll
                for (int n4 = 0; n4 < 4; n4++) {
                    const int nt = g * 4 + n4;
                    float e0 = ex2(acc[mt][nt][2 * u]);
                    float e1 = ex2(acc[mt][nt][2 * u + 1]);
                    if (DIAG) {
                        const int gi = i0 + wm * 32 + mt * 16 + (lane >> 2) + u * 8;
                        const int gj = j0 + wn * 64 + nt * 8 + (lane & 3) * 2;
                        if (gi == gj)     e0 = 0.f;
                        if (gi == gj + 1) e1 = 0.f;
                    }
                    const bool m0 = (cl0[n4] == rlab);
                    const bool m1 = (cl1[n4] == rlab);
                    tsum += e0 + e1;
                    if (m0) psum += e0;
                    if (m1) psum += e1;
                    if (!DIAG) {
                        ctot[n4][0] += e0;
                        ctot[n4][1] += e1;
                        if (m0) cpos[n4][0] += e0;
                        if (m1) cpos[n4][1] += e1;
                    }
                }
                tot[mt][u] += tsum;
                pos[mt][u] += psum;
            }

        if (!DIAG) {
            // reduce col partials over the 8 lanes sharing (lane&3) -> smem
#pragma unroll
            for (int n4 = 0; n4 < 4; n4++)
#pragma unroll
                for (int e = 0; e < 2; e++) {
                    float cp = cpos[n4][e], ct = ctot[n4][e];
                    cp += __shfl_xor_sync(0xFFFFFFFF, cp, 4);
                    cp += __shfl_xor_sync(0xFFFFFFFF, cp, 8);
                    cp += __shfl_xor_sync(0xFFFFFFFF, cp, 16);
                    ct += __shfl_xor_sync(0xFFFFFFFF, ct, 4);
                    ct += __shfl_xor_sync(0xFFFFFFFF, ct, 8);
                    ct += __shfl_xor_sync(0xFFFFFFFF, ct, 16);
                    if (lane < 4) {
                        int col = wn * 64 + (g * 4 + n4) * 8 + lane * 2 + e;
                        scol[(wm * 128 + col) * 2 + 0] = cp;
                        scol[(wm * 128 + col) * 2 + 1] = ct;
                    }
                }
        }
    }
}

// ---------------------------------------------------------------------------
// Kernel C: symmetric HMMA Gram. CTA it streams jt=(it+d)&31, d=0..15/16.
// ---------------------------------------------------------------------------
__global__ __launch_bounds__(256, 2) void k_gram() {
    extern __shared__ char sm[];
    const uint32_t sb = s2u(sm);
    unsigned char* lab8s = (unsigned char*)(sm + SM_LAB);
    float* scol = (float*)(sm + SM_CS);

    const int b    = blockIdx.y;
    const int it   = blockIdx.x;
    const int i0   = it * 128;
    const int tid  = threadIdx.x;
    const int wid  = tid >> 5;
    const int lane = tid & 31;
    const int wm   = wid & 3;
    const int wn   = wid >> 2;
    const int npair = (it < 16) ? 17 : 16;

    const __nv_bfloat16* vt = g_vt + (size_t)b * NN * CC;

#pragma unroll
    for (int t = 0; t < 8; t++) {
        int idx = tid + t * 256;
        int row = idx >> 4, c16 = idx & 15;
        cp16(sb + SM_A + row * ROWB + c16 * 16,
             vt + (size_t)(i0 + row) * CC + c16 * 8);
        cp16(sb + SM_B0 + row * ROWB + c16 * 16,
             vt + (size_t)(i0 + row) * CC + c16 * 8);
    }
    cp16(sb + SM_LAB + tid * 16, g_lab8 + (size_t)b * NN + tid * 16);
    cp_commit();
    cp_wait0();
    __syncthreads();

    int rl[2][2];
#pragma unroll
    for (int mt = 0; mt < 2; mt++)
#pragma unroll
        for (int u = 0; u < 2; u++)
            rl[mt][u] = (int)lab8s[i0 + wm * 32 + mt * 16 + (lane >> 2) + u * 8];

    float pos[2][2] = {{0.f, 0.f}, {0.f, 0.f}};
    float tot[2][2] = {{0.f, 0.f}, {0.f, 0.f}};

    for (int d = 0; d < npair; d++) {
        const int jt  = (it + d) & 31;
        const int cur = d & 1;
        if (d + 1 < npair) {
            const int j0n = ((it + d + 1) & 31) * 128;
            uint32_t bdst = sb + (cur ? SM_B0 : SM_B1);
#pragma unroll
            for (int t = 0; t < 8; t++) {
                int idx = tid + t * 256;
                int row = idx >> 4, c16 = idx & 15;
                cp16(bdst + row * ROWB + c16 * 16,
                     vt + (size_t)(j0n + row) * CC + c16 * 8);
            }
            cp_commit();
        }

        const uint32_t aB = sb + SM_A;
        const uint32_t bB = sb + (cur ? SM_B1 : SM_B0);
        const int j0 = jt * 128;

        if (d == 0)
            do_tile<true>(aB, bB, i0, j0, wm, wn, lane, rl, lab8s, pos, tot, scol);
        else
            do_tile<false>(aB, bB, i0, j0, wm, wn, lane, rl, lab8s, pos, tot, scol);

        __syncthreads();                    // scol complete
        if (d > 0 && tid < 128) {
            float p = scol[(0 * 128 + tid) * 2]     + scol[(1 * 128 + tid) * 2]
                    + scol[(2 * 128 + tid) * 2]     + scol[(3 * 128 + tid) * 2];
            float t = scol[(0 * 128 + tid) * 2 + 1] + scol[(1 * 128 + tid) * 2 + 1]
                    + scol[(2 * 128 + tid) * 2 + 1] + scol[(3 * 128 + tid) * 2 + 1];
            g_stage[((size_t)(b * 32 + jt) * NSLOT + 2 + (d - 1)) * 128 + tid]
                = make_float2(p, t);
        }
        cp_wait0();
        __syncthreads();                    // scol reads done; B buffer ready
    }

    // own-row sums -> slots 0 (wn=0) and 1 (wn=1)
#pragma unroll
    for (int mt = 0; mt < 2; mt++)
#pragma unroll
        for (int u = 0; u < 2; u++) {
            float p = pos[mt][u], t = tot[mt][u];
            p += __shfl_xor_sync(0xFFFFFFFF, p, 1);
            p += __shfl_xor_sync(0xFFFFFFFF, p, 2);
            t += __shfl_xor_sync(0xFFFFFFFF, t, 1);
            t += __shfl_xor_sync(0xFFFFFFFF, t, 2);
            if ((lane & 3) == 0) {
                int row = wm * 32 + mt * 16 + (lane >> 2) + u * 8;
                g_stage[((size_t)(b * 32 + it) * NSLOT + wn) * 128 + row]
                    = make_float2(p, t);
            }
        }
}

// ---------------------------------------------------------------------------
// Kernel D: combine staged partials (512 thr: 4 slot-stripes per row),
// per-row loss, block partial, fused final reduction (last block).
// ---------------------------------------------------------------------------
__global__ void k_final(float* __restrict__ out) {
    __shared__ float sp4[4][128], st4[4][128];
    __shared__ float red[512];
    __shared__ int amLast;
    const int blk = blockIdx.x;           // (b*32 + jt)
    const int b = blk >> 5, jt = blk & 31;
    const int t = threadIdx.x;            // 512 threads
    const int r = t & 127;                // row
    const int q = t >> 7;                 // slot stripe 0..3
    const float2* stg = g_stage + (size_t)blk * NSLOT * 128;

    float p = 0.f, tt = 0.f;
    // col slots 2..17, stripe q takes s = 2+q, 6+q, 10+q, 14+q
#pragma unroll
    for (int s = 2 + q; s < NSLOT; s += 4) {
        if (s == 17 && jt < 16) break;    // d=16 only valid for jt >= 16
        float2 v = stg[s * 128 + r];
        p += v.x; tt += v.y;
    }
    if (q < 2) {                          // own-row slots 0,1
        float2 v = stg[q * 128 + r];
        p += v.x; tt += v.y;
    }
    sp4[q][r] = p; st4[q][r] = tt;
    __syncthreads();

    if (t < 128) {
        float pp = sp4[0][t] + sp4[1][t] + sp4[2][t] + sp4[3][t];
        float tq = st4[0][t] + st4[1][t] + st4[2][t] + st4[3][t];
        int i = b * NN + jt * 128 + t;
        int l = (int)g_lab8[i];
        int cnt = g_cnt[b * NLAB + l];
        float pm = pp / (float)cnt;
        float nm = (tq - pp) / (float)(NN - cnt);
        red[t] = __logf((pm + nm) / pm);
    }
    __syncthreads();
    if (t < 64) red[t] += red[t + 64];
    __syncthreads();
    if (t < 32) {
        float v = red[t] + red[t + 32];
#pragma unroll
        for (int o = 16; o > 0; o >>= 1) v += __shfl_xor_sync(0xFFFFFFFF, v, o);
        if (t == 0) {
            g_part[blk] = v;
            __threadfence();
            amLast = (atomicAdd(&g_ctr, 1u) == (unsigned)(BB * 32 - 1));
        }
    }
    __syncthreads();
    if (amLast) {
        red[t] = (t < 256) ? g_part[t] : 0.f;
        __syncthreads();
        if (t < 128) red[t] += red[t + 128];
        __syncthreads();
        if (t < 64) red[t] += red[t + 64];
        __syncthreads();
        if (t < 32) {
            float v = red[t] + red[t + 32];
#pragma unroll
            for (int o = 16; o > 0; o >>= 1) v += __shfl_xor_sync(0xFFFFFFFF, v, o);
            if (t == 0) out[0] = v / (float)(BB * NN);
        }
    }
}

// ---------------------------------------------------------------------------
extern "C" void kernel_launch(void* const* d_in, const int* in_sizes, int n_in,
                              void* d_out, int out_size) {
    const float* f   = (const float*)d_in[0];
    const int*   lab = (const int*)d_in[1];
    float*       out = (float*)d_out;

    cudaFuncSetAttribute(k_norm, cudaFuncAttributeMaxDynamicSharedMemorySize,
                         NORM_SMEM);
    cudaFuncSetAttribute(k_gram, cudaFuncAttributeMaxDynamicSharedMemorySize,
                         SMEM_DYN);

    k_labels<<<BB, 256>>>(lab);
    k_norm<<<dim3(NN / 128, BB), 512, NORM_SMEM>>>(f);
    k_gram<<<dim3(32, BB), 256, SMEM_DYN>>>();
    k_final<<<BB * 32, 512>>>(out);
}

// round 15
// speedup vs baseline: 1.0381x; 1.0016x over previous
#include <cuda_runtime.h>
#include <cuda_bf16.h>
#include <math.h>
#include <stdint.h>

#define BB   8
#define CC   128
#define NN   4096
#define NLAB 16
// slots: 0..3 = own-row sums (half*2+wn); 4 + (d-1) = col sums, d=1..16
#define NSLOT 20

// ---------------------------------------------------------------------------
// Device scratch (no allocations allowed)
// ---------------------------------------------------------------------------
__device__ __nv_bfloat16 g_vt[BB * NN * CC];     // normalized (x sqrt(log2e)) [b][n][c]
__device__ unsigned char g_lab8[BB * NN];
__device__ int           g_cnt[BB * NLAB];
__device__ float2        g_stage[BB * 32 * NSLOT * 128];  // (pos, tot) partials
__device__ float         g_part[BB * 32];
__device__ unsigned int  g_ctr;

// ---------------------------------------------------------------------------
// smem layout for k_gram. Tile rows padded to 272B (conflict-free LDSM).
// ---------------------------------------------------------------------------
#define ROWB   272
#define TILEB  (128 * ROWB)          // 34816
#define SM_A   0
#define SM_B0  TILEB
#define SM_B1  (2 * TILEB)
#define SM_LAB (3 * TILEB)           // 4096 B labels
#define SM_CS  (SM_LAB + 4096)       // 4096 B col partials [4 wm][128 col][2]
#define SMEM_DYN (SM_CS + 4096)      // 112640 B -> 2 CTAs/SM

// k_norm smem: ts[128*129] + ssp[512] + srinv[128] floats
#define NORM_SMEM ((128 * 129 + 512 + 128) * 4)

// ---------------------------------------------------------------------------
// PTX helpers (plain sm_80+ features)
// ---------------------------------------------------------------------------
__device__ __forceinline__ uint32_t s2u(const void* p) {
    return (uint32_t)__cvta_generic_to_shared(p);
}
__device__ __forceinline__ void cp16(uint32_t dst, const void* src) {
    asm volatile("cp.async.cg.shared.global [%0], [%1], 16;" :: "r"(dst), "l"(src) : "memory");
}
__device__ __forceinline__ void cp_commit() { asm volatile("cp.async.commit_group;" ::: "memory"); }
__device__ __forceinline__ void cp_wait0()  { asm volatile("cp.async.wait_group 0;" ::: "memory"); }

__device__ __forceinline__ void ldsm4(uint32_t* r, uint32_t addr) {
    asm volatile("ldmatrix.sync.aligned.m8n8.x4.shared.b16 {%0,%1,%2,%3}, [%4];"
                 : "=r"(r[0]), "=r"(r[1]), "=r"(r[2]), "=r"(r[3]) : "r"(addr));
}
__device__ __forceinline__ void mma16816(float* c, const uint32_t* a,
                                         uint32_t b0, uint32_t b1) {
    asm volatile(
        "mma.sync.aligned.m16n8k16.row.col.f32.bf16.bf16.f32 "
        "{%0,%1,%2,%3}, {%4,%5,%6,%7}, {%8,%9}, {%0,%1,%2,%3};"
        : "+f"(c[0]), "+f"(c[1]), "+f"(c[2]), "+f"(c[3])
        : "r"(a[0]), "r"(a[1]), "r"(a[2]), "r"(a[3]), "r"(b0), "r"(b1));
}
__device__ __forceinline__ float ex2(float x) {
    float y; asm("ex2.approx.f32 %0, %1;" : "=f"(y) : "f"(x)); return y;
}

// ---------------------------------------------------------------------------
// Kernel A: labels -> uint8 copy + per-cloud histogram (+ counter reset)
// ---------------------------------------------------------------------------
__global__ void k_labels(const int* __restrict__ labels) {
    __shared__ int hist[NLAB];
    int b = blockIdx.x;
    if (b == 0 && threadIdx.x == 0) g_ctr = 0;
    if (threadIdx.x < NLAB) hist[threadIdx.x] = 0;
    __syncthreads();
    for (int n = threadIdx.x; n < NN; n += blockDim.x) {
        int l = labels[b * NN + n];
        g_lab8[b * NN + n] = (unsigned char)l;
        atomicAdd(&hist[l], 1);
    }
    __syncthreads();
    if (threadIdx.x < NLAB) g_cnt[b * NLAB + threadIdx.x] = hist[threadIdx.x];
}

// ---------------------------------------------------------------------------
// Kernel B: normalize (x sqrt(log2e)) + transpose + bf16: g_vt[b][n][c]
// ---------------------------------------------------------------------------
__global__ __launch_bounds__(512) void k_norm(const float* __restrict__ f) {
    extern __shared__ float ts[];               // [128][129]
    float* ssp   = ts + 128 * 129;              // [512] quarter sums
    float* srinv = ssp + 512;                   // [128]
    const int b = blockIdx.y, n0 = blockIdx.x * 128;
    const int tid = threadIdx.x;

    const float4* f4 = (const float4*)(f + (size_t)b * CC * NN);
    const int n0q = n0 >> 2;
    float4 v[8];
#pragma unroll
    for (int t = 0; t < 8; t++) {
        int idx = tid + t * 512;
        int k = idx >> 5, n4 = idx & 31;
        v[t] = f4[(size_t)k * (NN / 4) + n0q + n4];
    }
#pragma unroll
    for (int t = 0; t < 8; t++) {
        int idx = tid + t * 512;
        int k = idx >> 5, n4 = (idx & 31) << 2;
        ts[(n4 + 0) * 129 + k] = v[t].x;
        ts[(n4 + 1) * 129 + k] = v[t].y;
        ts[(n4 + 2) * 129 + k] = v[t].z;
        ts[(n4 + 3) * 129 + k] = v[t].w;
    }
    __syncthreads();

    {
        const int n = tid & 127, q = tid >> 7;
        float ss = 0.f;
#pragma unroll 8
        for (int k = 0; k < 32; k++) {
            float x = ts[n * 129 + q * 32 + k];
            ss = fmaf(x, x, ss);
        }
        ssp[tid] = ss;
    }
    __syncthreads();
    if (tid < 128) {
        float s = ssp[tid] + ssp[tid + 128] + ssp[tid + 256] + ssp[tid + 384];
        srinv[tid] = 1.2011224087864498f / fmaxf(sqrtf(s), 1e-12f);
    }
    __syncthreads();

    __nv_bfloat162* o2 = (__nv_bfloat162*)g_vt;
#pragma unroll
    for (int t = 0; t < 16; t++) {
        int idx = tid + t * 512;
        int n = idx >> 6, c2 = idx & 63;
        float r = srinv[n];
        float v0 = ts[n * 129 + 2 * c2] * r;
        float v1 = ts[n * 129 + 2 * c2 + 1] * r;
        o2[((size_t)b * NN + n0 + n) * 64 + c2] = __floats2bfloat162_rn(v0, v1);
    }
}

// ---------------------------------------------------------------------------
// One 128x128 tile, full 32x64 warp strip (A-fragments reused across cols).
// MMA + exp + row sums (registers) + col sums -> scol (smem).
// ---------------------------------------------------------------------------
template <bool DIAG>
__device__ __forceinline__ void do_tile(
    uint32_t aB, uint32_t bB, int i0, int j0,
    int wm, int wn, int lane,
    const int rl[2][2], const unsigned char* __restrict__ lab8s,
    float pos[2][2], float tot[2][2], float* __restrict__ scol)
{
    const int lrow = lane & 15;
    const int lkof = (lane >> 4) << 3;

    float acc[2][8][4];
#pragma unroll
    for (int mt = 0; mt < 2; mt++)
#pragma unroll
        for (int nt = 0; nt < 8; nt++)
#pragma unroll
            for (int r = 0; r < 4; r++) acc[mt][nt][r] = 0.f;

#pragma unroll
    for (int ks = 0; ks < 8; ks++) {
        const int k0 = ks * 16;
        uint32_t a[2][4], bq[4][4];
#pragma unroll
        for (int mt = 0; mt < 2; mt++) {
            int row = wm * 32 + mt * 16 + lrow;
            ldsm4(a[mt], aB + row * ROWB + (k0 + lkof) * 2);
        }
#pragma unroll
        for (int q = 0; q < 4; q++) {
            int row = wn * 64 + q * 16 + lrow;
            ldsm4(bq[q], bB + row * ROWB + (k0 + lkof) * 2);
        }
#pragma unroll
        for (int mt = 0; mt < 2; mt++)
#pragma unroll
            for (int q = 0; q < 4; q++) {
                mma16816(acc[mt][2 * q],     a[mt], bq[q][0], bq[q][2]);
                mma16816(acc[mt][2 * q + 1], a[mt], bq[q][1], bq[q][3]);
            }
    }

#pragma unroll
    for (int g = 0; g < 2; g++) {
        int cl0[4], cl1[4];
#pragma unroll
        for (int n4 = 0; n4 < 4; n4++) {
            int jj = j0 + wn * 64 + (g * 4 + n4) * 8 + (lane & 3) * 2;
            cl0[n4] = (int)lab8s[jj];
            cl1[n4] = (int)lab8s[jj + 1];
        }

        float cpos[4][2], ctot[4][2];
        if (!DIAG) {
#pragma unroll
            for (int n4 = 0; n4 < 4; n4++) {
                cpos[n4][0] = cpos[n4][1] = 0.f;
                ctot[n4][0] = ctot[n4][1] = 0.f;
            }
        }

#pragma unroll
        for (int mt = 0; mt < 2; mt++)
#pragma unroll
            for (int u = 0; u < 2; u++) {
                const int rlab = rl[mt][u];
                float tsum = 0.f, psum = 0.f;
#pragma unroll
                for (int n4 = 0; n4 < 4; n4++) {
                    const int nt = g * 4 + n4;
                    float e0 = ex2(acc[mt][nt][2 * u]);
                    float e1 = ex2(acc[mt][nt][2 * u + 1]);
                    if (DIAG) {
                        const int gi = i0 + wm * 32 + mt * 16 + (lane >> 2) + u * 8;
                        const int gj = j0 + wn * 64 + nt * 8 + (lane & 3) * 2;
                        if (gi == gj)     e0 = 0.f;
                        if (gi == gj + 1) e1 = 0.f;
                    }
                    const bool m0 = (cl0[n4] == rlab);
                    const bool m1 = (cl1[n4] == rlab);
                    tsum += e0 + e1;
                    if (m0) psum += e0;
                    if (m1) psum += e1;
                    if (!DIAG) {
                        ctot[n4][0] += e0;
                        ctot[n4][1] += e1;
                        if (m0) cpos[n4][0] += e0;
                        if (m1) cpos[n4][1] += e1;
                    }
                }
                tot[mt][u] += tsum;
                pos[mt][u] += psum;
            }

        if (!DIAG) {
#pragma unroll
            for (int n4 = 0; n4 < 4; n4++)
#pragma unroll
                for (int e = 0; e < 2; e++) {
                    float cp = cpos[n4][e], ct = ctot[n4][e];
                    cp += __shfl_xor_sync(0xFFFFFFFF, cp, 4);
                    cp += __shfl_xor_sync(0xFFFFFFFF, cp, 8);
                    cp += __shfl_xor_sync(0xFFFFFFFF, cp, 16);
                    ct += __shfl_xor_sync(0xFFFFFFFF, ct, 4);
                    ct += __shfl_xor_sync(0xFFFFFFFF, ct, 8);
                    ct += __shfl_xor_sync(0xFFFFFFFF, ct, 16);
                    if (lane < 4) {
                        int col = wn * 64 + (g * 4 + n4) * 8 + lane * 2 + e;
                        scol[(wm * 128 + col) * 2 + 0] = cp;
                        scol[(wm * 128 + col) * 2 + 1] = ct;
                    }
                }
        }
    }
}

// ---------------------------------------------------------------------------
// Kernel C: symmetric HMMA Gram, split 2 CTAs per row-tile.
// grid.x = 64: it = x>>1, half = x&1. Half 0 does d=0..ceil(np/2)-1 (incl
// diag), half 1 does the rest. 512 CTAs of 8-9 tiles each -> fills all 296
// occ-2 slots with fine-grained work stealing.
// ---------------------------------------------------------------------------
__global__ __launch_bounds__(256, 2) void k_gram() {
    extern __shared__ char sm[];
    const uint32_t sb = s2u(sm);
    unsigned char* lab8s = (unsigned char*)(sm + SM_LAB);
    float* scol = (float*)(sm + SM_CS);

    const int b    = blockIdx.y;
    const int it   = blockIdx.x >> 1;
    const int half = blockIdx.x & 1;
    const int i0   = it * 128;
    const int tid  = threadIdx.x;
    const int wid  = tid >> 5;
    const int lane = tid & 31;
    const int wm   = wid & 3;
    const int wn   = wid >> 2;
    const int npair = (it < 16) ? 17 : 16;
    const int dh   = (npair + 1) >> 1;           // 9 or 8
    const int d0   = half ? dh : 0;
    const int d1   = half ? npair : dh;

    const __nv_bfloat16* vt = g_vt + (size_t)b * NN * CC;
    const int j00 = ((it + d0) & 31) * 128;      // first B tile rows

#pragma unroll
    for (int t = 0; t < 8; t++) {
        int idx = tid + t * 256;
        int row = idx >> 4, c16 = idx & 15;
        cp16(sb + SM_A + row * ROWB + c16 * 16,
             vt + (size_t)(i0 + row) * CC + c16 * 8);
        cp16(sb + SM_B0 + row * ROWB + c16 * 16,
             vt + (size_t)(j00 + row) * CC + c16 * 8);
    }
    cp16(sb + SM_LAB + tid * 16, g_lab8 + (size_t)b * NN + tid * 16);
    cp_commit();
    cp_wait0();
    __syncthreads();

    int rl[2][2];
#pragma unroll
    for (int mt = 0; mt < 2; mt++)
#pragma unroll
        for (int u = 0; u < 2; u++)
            rl[mt][u] = (int)lab8s[i0 + wm * 32 + mt * 16 + (lane >> 2) + u * 8];

    float pos[2][2] = {{0.f, 0.f}, {0.f, 0.f}};
    float tot[2][2] = {{0.f, 0.f}, {0.f, 0.f}};

    for (int d = d0; d < d1; d++) {
        const int jt  = (it + d) & 31;
        const int cur = (d - d0) & 1;
        if (d + 1 < d1) {
            const int j0n = ((it + d + 1) & 31) * 128;
            uint32_t bdst = sb + (cur ? SM_B0 : SM_B1);
#pragma unroll
            for (int t = 0; t < 8; t++) {
                int idx = tid + t * 256;
                int row = idx >> 4, c16 = idx & 15;
                cp16(bdst + row * ROWB + c16 * 16,
                     vt + (size_t)(j0n + row) * CC + c16 * 8);
            }
            cp_commit();
        }

        const uint32_t aB = sb + SM_A;
        const uint32_t bB = sb + (cur ? SM_B1 : SM_B0);
        const int j0 = jt * 128;

        if (d == 0)
            do_tile<true>(aB, bB, i0, j0, wm, wn, lane, rl, lab8s, pos, tot, scol);
        else
            do_tile<false>(aB, bB, i0, j0, wm, wn, lane, rl, lab8s, pos, tot, scol);

        __syncthreads();                    // scol complete
        if (d > 0 && tid < 128) {
            float p = scol[(0 * 128 + tid) * 2]     + scol[(1 * 128 + tid) * 2]
                    + scol[(2 * 128 + tid) * 2]     + scol[(3 * 128 + tid) * 2];
            float t = scol[(0 * 128 + tid) * 2 + 1] + scol[(1 * 128 + tid) * 2 + 1]
                    + scol[(2 * 128 + tid) * 2 + 1] + scol[(3 * 128 + tid) * 2 + 1];
            g_stage[((size_t)(b * 32 + jt) * NSLOT + 4 + (d - 1)) * 128 + tid]
                = make_float2(p, t);
        }
        cp_wait0();
        __syncthreads();                    // scol reads done; B buffer ready
    }

    // own-row sums -> slots half*2 + wn (0..3)
#pragma unroll
    for (int mt = 0; mt < 2; mt++)
#pragma unroll
        for (int u = 0; u < 2; u++) {
            float p = pos[mt][u], t = tot[mt][u];
            p += __shfl_xor_sync(0xFFFFFFFF, p, 1);
            p += __shfl_xor_sync(0xFFFFFFFF, p, 2);
            t += __shfl_xor_sync(0xFFFFFFFF, t, 1);
            t += __shfl_xor_sync(0xFFFFFFFF, t, 2);
            if ((lane & 3) == 0) {
                int row = wm * 32 + mt * 16 + (lane >> 2) + u * 8;
                g_stage[((size_t)(b * 32 + it) * NSLOT + half * 2 + wn) * 128 + row]
                    = make_float2(p, t);
            }
        }
}

// ---------------------------------------------------------------------------
// Kernel D: combine staged partials (512 thr: 4 slot-stripes per row),
// per-row loss, block partial, fused final reduction (last block).
// ---------------------------------------------------------------------------
__global__ void k_final(float* __restrict__ out) {
    __shared__ float sp4[4][128], st4[4][128];
    __shared__ float red[512];
    __shared__ int amLast;
    const int blk = blockIdx.x;           // (b*32 + jt)
    const int b = blk >> 5, jt = blk & 31;
    const int t = threadIdx.x;            // 512 threads
    const int r = t & 127;                // row
    const int q = t >> 7;                 // slot stripe 0..3
    const float2* stg = g_stage + (size_t)blk * NSLOT * 128;

    float p = 0.f, tt = 0.f;
    // col slots 4..19, stripe q takes s = 4+q, 8+q, 12+q, 16+q
#pragma unroll
    for (int s = 4 + q; s < NSLOT; s += 4) {
        if (s == 19 && jt < 16) break;    // d=16 only valid for jt >= 16
        float2 v = stg[s * 128 + r];
        p += v.x; tt += v.y;
    }
    {                                     // own-row slots 0..3, one per stripe
        float2 v = stg[q * 128 + r];
        p += v.x; tt += v.y;
    }
    sp4[q][r] = p; st4[q][r] = tt;
    __syncthreads();

    if (t < 128) {
        float pp = sp4[0][t] + sp4[1][t] + sp4[2][t] + sp4[3][t];
        float tq = st4[0][t] + st4[1][t] + st4[2][t] + st4[3][t];
        int i = b * NN + jt * 128 + t;
        int l = (int)g_lab8[i];
        int cnt = g_cnt[b * NLAB + l];
        float pm = pp / (float)cnt;
        float nm = (tq - pp) / (float)(NN - cnt);
        red[t] = __logf((pm + nm) / pm);
    }
    __syncthreads();
    if (t < 64) red[t] += red[t + 64];
    __syncthreads();
    if (t < 32) {
        float v = red[t] + red[t + 32];
#pragma unroll
        for (int o = 16; o > 0; o >>= 1) v += __shfl_xor_sync(0xFFFFFFFF, v, o);
        if (t == 0) {
            g_part[blk] = v;
            __threadfence();
            amLast = (atomicAdd(&g_ctr, 1u) == (unsigned)(BB * 32 - 1));
        }
    }
    __syncthreads();
    if (amLast) {
        red[t] = (t < 256) ? g_part[t] : 0.f;
        __syncthreads();
        if (t < 128) red[t] += red[t + 128];
        __syncthreads();
        if (t < 64) red[t] += red[t + 64];
        __syncthreads();
        if (t < 32) {
            float v = red[t] + red[t + 32];
#pragma unroll
            for (int o = 16; o > 0; o >>= 1) v += __shfl_xor_sync(0xFFFFFFFF, v, o);
            if (t == 0) out[0] = v / (float)(BB * NN);
        }
    }
}

// ---------------------------------------------------------------------------
extern "C" void kernel_launch(void* const* d_in, const int* in_sizes, int n_in,
                              void* d_out, int out_size) {
    const float* f   = (const float*)d_in[0];
    const int*   lab = (const int*)d_in[1];
    float*       out = (float*)d_out;

    cudaFuncSetAttribute(k_norm, cudaFuncAttributeMaxDynamicSharedMemorySize,
                         NORM_SMEM);
    cudaFuncSetAttribute(k_gram, cudaFuncAttributeMaxDynamicSharedMemorySize,
                         SMEM_DYN);

    k_labels<<<BB, 256>>>(lab);
    k_norm<<<dim3(NN / 128, BB), 512, NORM_SMEM>>>(f);
    k_gram<<<dim3(64, BB), 256, SMEM_DYN>>>();
    k_final<<<BB * 32, 512>>>(out);
}

// round 16
// speedup vs baseline: 1.0583x; 1.0194x over previous
#include <cuda_runtime.h>
#include <cuda_bf16.h>
#include <math.h>
#include <stdint.h>

#define BB   8
#define CC   128
#define NN   4096
#define NLAB 16
// slots: 0..3 = own-row sums (half*2+wn); 4 + (d-1) = col sums, d=1..16
#define NSLOT 20

// ---------------------------------------------------------------------------
// Device scratch (no allocations allowed)
// ---------------------------------------------------------------------------
__device__ __nv_bfloat16 g_vt[BB * NN * CC];     // normalized (x sqrt(log2e)) [b][n][c]
__device__ unsigned char g_lab8[BB * NN];
__device__ int           g_cnt[BB * NLAB];
__device__ float2        g_stage[BB * 32 * NSLOT * 128];  // (pos, tot) partials
__device__ float         g_part[BB * 32];
__device__ unsigned int  g_ctr;

// ---------------------------------------------------------------------------
// smem layout for k_gram. Tile rows padded to 272B (conflict-free LDSM).
// ---------------------------------------------------------------------------
#define ROWB   272
#define TILEB  (128 * ROWB)          // 34816
#define SM_A   0
#define SM_B0  TILEB
#define SM_B1  (2 * TILEB)
#define SM_LAB (3 * TILEB)           // 4096 B labels
#define SM_CS  (SM_LAB + 4096)       // 4096 B col partials float2[4 wm][128 col]
#define SMEM_DYN (SM_CS + 4096)      // 112640 B -> 2 CTAs/SM

// k_norm smem: ts[128*129] + ssp[512] + srinv[128] floats
#define NORM_SMEM ((128 * 129 + 512 + 128) * 4)

// ---------------------------------------------------------------------------
// PTX helpers
// ---------------------------------------------------------------------------
__device__ __forceinline__ uint32_t s2u(const void* p) {
    return (uint32_t)__cvta_generic_to_shared(p);
}
__device__ __forceinline__ void cp16(uint32_t dst, const void* src) {
    asm volatile("cp.async.cg.shared.global [%0], [%1], 16;" :: "r"(dst), "l"(src) : "memory");
}
__device__ __forceinline__ void cp_commit() { asm volatile("cp.async.commit_group;" ::: "memory"); }
__device__ __forceinline__ void cp_wait0()  { asm volatile("cp.async.wait_group 0;" ::: "memory"); }

__device__ __forceinline__ void ldsm4(uint32_t* r, uint32_t addr) {
    asm volatile("ldmatrix.sync.aligned.m8n8.x4.shared.b16 {%0,%1,%2,%3}, [%4];"
                 : "=r"(r[0]), "=r"(r[1]), "=r"(r[2]), "=r"(r[3]) : "r"(addr));
}
__device__ __forceinline__ void mma16816(float* c, const uint32_t* a,
                                         uint32_t b0, uint32_t b1) {
    asm volatile(
        "mma.sync.aligned.m16n8k16.row.col.f32.bf16.bf16.f32 "
        "{%0,%1,%2,%3}, {%4,%5,%6,%7}, {%8,%9}, {%0,%1,%2,%3};"
        : "+f"(c[0]), "+f"(c[1]), "+f"(c[2]), "+f"(c[3])
        : "r"(a[0]), "r"(a[1]), "r"(a[2]), "r"(a[3]), "r"(b0), "r"(b1));
}
__device__ __forceinline__ float ex2(float x) {
    float y; asm("ex2.approx.f32 %0, %1;" : "=f"(y) : "f"(x)); return y;
}
// Blackwell packed f32x2 add (base sm_100 ISA feature)
__device__ __forceinline__ void addx2(float2& a, const float2& b) {
    unsigned long long* pa = reinterpret_cast<unsigned long long*>(&a);
    const unsigned long long* pb = reinterpret_cast<const unsigned long long*>(&b);
    asm("add.rn.f32x2 %0, %0, %1;" : "+l"(*pa) : "l"(*pb));
}

// ---------------------------------------------------------------------------
// Kernel A: labels -> uint8 copy + per-cloud histogram (+ counter reset)
// ---------------------------------------------------------------------------
__global__ void k_labels(const int* __restrict__ labels) {
    __shared__ int hist[NLAB];
    int b = blockIdx.x;
    if (b == 0 && threadIdx.x == 0) g_ctr = 0;
    if (threadIdx.x < NLAB) hist[threadIdx.x] = 0;
    __syncthreads();
    for (int n = threadIdx.x; n < NN; n += blockDim.x) {
        int l = labels[b * NN + n];
        g_lab8[b * NN + n] = (unsigned char)l;
        atomicAdd(&hist[l], 1);
    }
    __syncthreads();
    if (threadIdx.x < NLAB) g_cnt[b * NLAB + threadIdx.x] = hist[threadIdx.x];
}

// ---------------------------------------------------------------------------
// Kernel B: normalize (x sqrt(log2e)) + transpose + bf16: g_vt[b][n][c]
// ---------------------------------------------------------------------------
__global__ __launch_bounds__(512) void k_norm(const float* __restrict__ f) {
    extern __shared__ float ts[];               // [128][129]
    float* ssp   = ts + 128 * 129;              // [512] quarter sums
    float* srinv = ssp + 512;                   // [128]
    const int b = blockIdx.y, n0 = blockIdx.x * 128;
    const int tid = threadIdx.x;

    const float4* f4 = (const float4*)(f + (size_t)b * CC * NN);
    const int n0q = n0 >> 2;
    float4 v[8];
#pragma unroll
    for (int t = 0; t < 8; t++) {
        int idx = tid + t * 512;
        int k = idx >> 5, n4 = idx & 31;
        v[t] = f4[(size_t)k * (NN / 4) + n0q + n4];
    }
#pragma unroll
    for (int t = 0; t < 8; t++) {
        int idx = tid + t * 512;
        int k = idx >> 5, n4 = (idx & 31) << 2;
        ts[(n4 + 0) * 129 + k] = v[t].x;
        ts[(n4 + 1) * 129 + k] = v[t].y;
        ts[(n4 + 2) * 129 + k] = v[t].z;
        ts[(n4 + 3) * 129 + k] = v[t].w;
    }
    __syncthreads();

    {
        const int n = tid & 127, q = tid >> 7;
        float ss = 0.f;
#pragma unroll 8
        for (int k = 0; k < 32; k++) {
            float x = ts[n * 129 + q * 32 + k];
            ss = fmaf(x, x, ss);
        }
        ssp[tid] = ss;
    }
    __syncthreads();
    if (tid < 128) {
        float s = ssp[tid] + ssp[tid + 128] + ssp[tid + 256] + ssp[tid + 384];
        srinv[tid] = 1.2011224087864498f / fmaxf(sqrtf(s), 1e-12f);
    }
    __syncthreads();

    __nv_bfloat162* o2 = (__nv_bfloat162*)g_vt;
#pragma unroll
    for (int t = 0; t < 16; t++) {
        int idx = tid + t * 512;
        int n = idx >> 6, c2 = idx & 63;
        float r = srinv[n];
        float v0 = ts[n * 129 + 2 * c2] * r;
        float v1 = ts[n * 129 + 2 * c2 + 1] * r;
        o2[((size_t)b * NN + n0 + n) * 64 + c2] = __floats2bfloat162_rn(v0, v1);
    }
}

// ---------------------------------------------------------------------------
// One 128x128 tile, full 32x64 warp strip. MMA + exp + row sums (packed) +
// col sums -> scol (float2 smem). f32x2 packed adds on unconditional paths.
// ---------------------------------------------------------------------------
template <bool DIAG>
__device__ __forceinline__ void do_tile(
    uint32_t aB, uint32_t bB, int i0, int j0,
    int wm, int wn, int lane,
    const int rl[2][2], const unsigned char* __restrict__ lab8s,
    float pos[2][2], float tot[2][2], float2* __restrict__ scol)
{
    const int lrow = lane & 15;
    const int lkof = (lane >> 4) << 3;

    float acc[2][8][4];
#pragma unroll
    for (int mt = 0; mt < 2; mt++)
#pragma unroll
        for (int nt = 0; nt < 8; nt++)
#pragma unroll
            for (int r = 0; r < 4; r++) acc[mt][nt][r] = 0.f;

#pragma unroll
    for (int ks = 0; ks < 8; ks++) {
        const int k0 = ks * 16;
        uint32_t a[2][4], bq[4][4];
#pragma unroll
        for (int mt = 0; mt < 2; mt++) {
            int row = wm * 32 + mt * 16 + lrow;
            ldsm4(a[mt], aB + row * ROWB + (k0 + lkof) * 2);
        }
#pragma unroll
        for (int q = 0; q < 4; q++) {
            int row = wn * 64 + q * 16 + lrow;
            ldsm4(bq[q], bB + row * ROWB + (k0 + lkof) * 2);
        }
#pragma unroll
        for (int mt = 0; mt < 2; mt++)
#pragma unroll
            for (int q = 0; q < 4; q++) {
                mma16816(acc[mt][2 * q],     a[mt], bq[q][0], bq[q][2]);
                mma16816(acc[mt][2 * q + 1], a[mt], bq[q][1], bq[q][3]);
            }
    }

#pragma unroll
    for (int g = 0; g < 2; g++) {
        int cl0[4], cl1[4];
#pragma unroll
        for (int n4 = 0; n4 < 4; n4++) {
            int jj = j0 + wn * 64 + (g * 4 + n4) * 8 + (lane & 3) * 2;
            cl0[n4] = (int)lab8s[jj];
            cl1[n4] = (int)lab8s[jj + 1];
        }

        float cpos[4][2];
        float2 ctot2[4];
        if (!DIAG) {
#pragma unroll
            for (int n4 = 0; n4 < 4; n4++) {
                cpos[n4][0] = cpos[n4][1] = 0.f;
                ctot2[n4] = make_float2(0.f, 0.f);
            }
        }

#pragma unroll
        for (int mt = 0; mt < 2; mt++)
#pragma unroll
            for (int u = 0; u < 2; u++) {
                const int rlab = rl[mt][u];
                float2 tsv = make_float2(0.f, 0.f);
                float psum = 0.f;
#pragma unroll
                for (int n4 = 0; n4 < 4; n4++) {
                    const int nt = g * 4 + n4;
                    float2 e;
                    e.x = ex2(acc[mt][nt][2 * u]);
                    e.y = ex2(acc[mt][nt][2 * u + 1]);
                    if (DIAG) {
                        const int gi = i0 + wm * 32 + mt * 16 + (lane >> 2) + u * 8;
                        const int gj = j0 + wn * 64 + nt * 8 + (lane & 3) * 2;
                        if (gi == gj)     e.x = 0.f;
                        if (gi == gj + 1) e.y = 0.f;
                    }
                    const bool m0 = (cl0[n4] == rlab);
                    const bool m1 = (cl1[n4] == rlab);
                    addx2(tsv, e);
                    if (m0) psum += e.x;
                    if (m1) psum += e.y;
                    if (!DIAG) {
                        addx2(ctot2[n4], e);
                        if (m0) cpos[n4][0] += e.x;
                        if (m1) cpos[n4][1] += e.y;
                    }
                }
                tot[mt][u] += tsv.x + tsv.y;
                pos[mt][u] += psum;
            }

        if (!DIAG) {
            // reduce col partials over the 8 lanes sharing (lane&3) -> smem
#pragma unroll
            for (int n4 = 0; n4 < 4; n4++)
#pragma unroll
                for (int e_ = 0; e_ < 2; e_++) {
                    float cp = cpos[n4][e_];
                    float ct = e_ ? ctot2[n4].y : ctot2[n4].x;
                    cp += __shfl_xor_sync(0xFFFFFFFF, cp, 4);
                    cp += __shfl_xor_sync(0xFFFFFFFF, cp, 8);
                    cp += __shfl_xor_sync(0xFFFFFFFF, cp, 16);
                    ct += __shfl_xor_sync(0xFFFFFFFF, ct, 4);
                    ct += __shfl_xor_sync(0xFFFFFFFF, ct, 8);
                    ct += __shfl_xor_sync(0xFFFFFFFF, ct, 16);
                    if (lane < 4) {
                        int col = wn * 64 + (g * 4 + n4) * 8 + lane * 2 + e_;
                        scol[wm * 128 + col] = make_float2(cp, ct);
                    }
                }
        }
    }
}

// ---------------------------------------------------------------------------
// Kernel C: symmetric HMMA Gram, split 2 CTAs per row-tile (grid.x = 64).
// ---------------------------------------------------------------------------
__global__ __launch_bounds__(256, 2) void k_gram() {
    extern __shared__ char sm[];
    const uint32_t sb = s2u(sm);
    unsigned char* lab8s = (unsigned char*)(sm + SM_LAB);
    float2* scol = (float2*)(sm + SM_CS);

    const int b    = blockIdx.y;
    const int it   = blockIdx.x >> 1;
    const int half = blockIdx.x & 1;
    const int i0   = it * 128;
    const int tid  = threadIdx.x;
    const int wid  = tid >> 5;
    const int lane = tid & 31;
    const int wm   = wid & 3;
    const int wn   = wid >> 2;
    const int npair = (it < 16) ? 17 : 16;
    const int dh   = (npair + 1) >> 1;
    const int d0   = half ? dh : 0;
    const int d1   = half ? npair : dh;

    const __nv_bfloat16* vt = g_vt + (size_t)b * NN * CC;
    const int j00 = ((it + d0) & 31) * 128;

#pragma unroll
    for (int t = 0; t < 8; t++) {
        int idx = tid + t * 256;
        int row = idx >> 4, c16 = idx & 15;
        cp16(sb + SM_A + row * ROWB + c16 * 16,
             vt + (size_t)(i0 + row) * CC + c16 * 8);
        cp16(sb + SM_B0 + row * ROWB + c16 * 16,
             vt + (size_t)(j00 + row) * CC + c16 * 8);
    }
    cp16(sb + SM_LAB + tid * 16, g_lab8 + (size_t)b * NN + tid * 16);
    cp_commit();
    cp_wait0();
    __syncthreads();

    int rl[2][2];
#pragma unroll
    for (int mt = 0; mt < 2; mt++)
#pragma unroll
        for (int u = 0; u < 2; u++)
            rl[mt][u] = (int)lab8s[i0 + wm * 32 + mt * 16 + (lane >> 2) + u * 8];

    float pos[2][2] = {{0.f, 0.f}, {0.f, 0.f}};
    float tot[2][2] = {{0.f, 0.f}, {0.f, 0.f}};

    for (int d = d0; d < d1; d++) {
        const int jt  = (it + d) & 31;
        const int cur = (d - d0) & 1;
        if (d + 1 < d1) {
            const int j0n = ((it + d + 1) & 31) * 128;
            uint32_t bdst = sb + (cur ? SM_B0 : SM_B1);
#pragma unroll
            for (int t = 0; t < 8; t++) {
                int idx = tid + t * 256;
                int row = idx >> 4, c16 = idx & 15;
                cp16(bdst + row * ROWB + c16 * 16,
                     vt + (size_t)(j0n + row) * CC + c16 * 8);
            }
            cp_commit();
        }

        const uint32_t aB = sb + SM_A;
        const uint32_t bB = sb + (cur ? SM_B1 : SM_B0);
        const int j0 = jt * 128;

        if (d == 0)
            do_tile<true>(aB, bB, i0, j0, wm, wn, lane, rl, lab8s, pos, tot, scol);
        else
            do_tile<false>(aB, bB, i0, j0, wm, wn, lane, rl, lab8s, pos, tot, scol);

        __syncthreads();                    // scol complete
        if (d > 0 && tid < 128) {
            float2 s0 = scol[0 * 128 + tid];
            float2 s1 = scol[1 * 128 + tid];
            float2 s2 = scol[2 * 128 + tid];
            float2 s3 = scol[3 * 128 + tid];
            g_stage[((size_t)(b * 32 + jt) * NSLOT + 4 + (d - 1)) * 128 + tid]
                = make_float2(s0.x + s1.x + s2.x + s3.x,
                              s0.y + s1.y + s2.y + s3.y);
        }
        cp_wait0();
        __syncthreads();                    // scol reads done; B buffer ready
    }

    // own-row sums -> slots half*2 + wn (0..3)
#pragma unroll
    for (int mt = 0; mt < 2; mt++)
#pragma unroll
        for (int u = 0; u < 2; u++) {
            float p = pos[mt][u], t = tot[mt][u];
            p += __shfl_xor_sync(0xFFFFFFFF, p, 1);
            p += __shfl_xor_sync(0xFFFFFFFF, p, 2);
            t += __shfl_xor_sync(0xFFFFFFFF, t, 1);
            t += __shfl_xor_sync(0xFFFFFFFF, t, 2);
            if ((lane & 3) == 0) {
                int row = wm * 32 + mt * 16 + (lane >> 2) + u * 8;
                g_stage[((size_t)(b * 32 + it) * NSLOT + half * 2 + wn) * 128 + row]
                    = make_float2(p, t);
            }
        }
}

// ---------------------------------------------------------------------------
// Kernel D: combine staged partials (512 thr: 4 slot-stripes per row),
// per-row loss, block partial, fused final reduction (last block).
// ---------------------------------------------------------------------------
__global__ void k_final(float* __restrict__ out) {
    __shared__ float sp4[4][128], st4[4][128];
    __shared__ float red[512];
    __shared__ int amLast;
    const int blk = blockIdx.x;           // (b*32 + jt)
    const int b = blk >> 5, jt = blk & 31;
    const int t = threadIdx.x;            // 512 threads
    const int r = t & 127;                // row
    const int q = t >> 7;                 // slot stripe 0..3
    const float2* stg = g_stage + (size_t)blk * NSLOT * 128;

    float p = 0.f, tt = 0.f;
#pragma unroll
    for (int s = 4 + q; s < NSLOT; s += 4) {
        if (s == 19 && jt < 16) break;    // d=16 only valid for jt >= 16
        float2 v = stg[s * 128 + r];
        p += v.x; tt += v.y;
    }
    {                                     // own-row slots 0..3, one per stripe
        float2 v = stg[q * 128 + r];
        p += v.x; tt += v.y;
    }
    sp4[q][r] = p; st4[q][r] = tt;
    __syncthreads();

    if (t < 128) {
        float pp = sp4[0][t] + sp4[1][t] + sp4[2][t] + sp4[3][t];
        float tq = st4[0][t] + st4[1][t] + st4[2][t] + st4[3][t];
        int i = b * NN + jt * 128 + t;
        int l = (int)g_lab8[i];
        int cnt = g_cnt[b * NLAB + l];
        float pm = pp / (float)cnt;
        float nm = (tq - pp) / (float)(NN - cnt);
        red[t] = __logf((pm + nm) / pm);
    }
    __syncthreads();
    if (t < 64) red[t] += red[t + 64];
    __syncthreads();
    if (t < 32) {
        float v = red[t] + red[t + 32];
#pragma unroll
        for (int o = 16; o > 0; o >>= 1) v += __shfl_xor_sync(0xFFFFFFFF, v, o);
        if (t == 0) {
            g_part[blk] = v;
            __threadfence();
            amLast = (atomicAdd(&g_ctr, 1u) == (unsigned)(BB * 32 - 1));
        }
    }
    __syncthreads();
    if (amLast) {
        red[t] = (t < 256) ? g_part[t] : 0.f;
        __syncthreads();
        if (t < 128) red[t] += red[t + 128];
        __syncthreads();
        if (t < 64) red[t] += red[t + 64];
        __syncthreads();
        if (t < 32) {
            float v = red[t] + red[t + 32];
#pragma unroll
            for (int o = 16; o > 0; o >>= 1) v += __shfl_xor_sync(0xFFFFFFFF, v, o);
            if (t == 0) out[0] = v / (float)(BB * NN);
        }
    }
}

// ---------------------------------------------------------------------------
extern "C" void kernel_launch(void* const* d_in, const int* in_sizes, int n_in,
                              void* d_out, int out_size) {
    const float* f   = (const float*)d_in[0];
    const int*   lab = (const int*)d_in[1];
    float*       out = (float*)d_out;

    cudaFuncSetAttribute(k_norm, cudaFuncAttributeMaxDynamicSharedMemorySize,
                         NORM_SMEM);
    cudaFuncSetAttribute(k_gram, cudaFuncAttributeMaxDynamicSharedMemorySize,
                         SMEM_DYN);

    k_labels<<<BB, 256>>>(lab);
    k_norm<<<dim3(NN / 128, BB), 512, NORM_SMEM>>>(f);
    k_gram<<<dim3(64, BB), 256, SMEM_DYN>>>();
    k_final<<<BB * 32, 512>>>(out);
}